// round 15
// baseline (speedup 1.0000x reference)
#include <cuda_runtime.h>
#include <cuda_fp16.h>
#include <stdint.h>

#define BATCH 32
#define NPOS  8732
#define CLS_OFF ((size_t)BATCH * NPOS * 4)

// static scratch
__device__ __half g_xt[37412864];
__device__ __half g_wt[12695040];
__device__ float  g_bias[2850];

// per-level tables (L0..L5)
__constant__ int    c_cum[7]   = {0, 1083, 1538, 1663, 1698, 1707, 1710};
__constant__ int    c_ntO[6]   = {3, 5, 5, 5, 3, 3};
__constant__ int    c_C[6]     = {512, 1024, 512, 256, 256, 256};
__constant__ int    c_S[6]     = {38, 19, 10, 5, 3, 1};
__constant__ int    c_A[6]     = {4, 6, 6, 6, 4, 4};
__constant__ int    c_P[6]     = {0, 5776, 7942, 8542, 8692, 8728};
__constant__ int    c_boff[6]  = {0, 380, 950, 1520, 2090, 2470};
__constant__ size_t c_xoff[6]  = {0, 23658496, 35487744, 37126144, 37330944, 37404672};
__constant__ size_t c_woff[6]  = {0, 1751040, 7004160, 9630720, 10944000, 11819520};

__device__ __forceinline__ uint32_t smem_u32(const void* p) {
    uint32_t r;
    asm("{ .reg .u64 t; cvta.to.shared.u64 t, %1; cvt.u32.u64 %0, t; }" : "=r"(r) : "l"(p));
    return r;
}
__device__ __forceinline__ void cp16(uint32_t dst, const void* src, uint32_t sz) {
    asm volatile("cp.async.cg.shared.global [%0], [%1], 16, %2;"
                 :: "r"(dst), "l"(src), "r"(sz) : "memory");
}
__device__ __forceinline__ void cp_commit() { asm volatile("cp.async.commit_group;" ::: "memory"); }
__device__ __forceinline__ void cp_wait1()  { asm volatile("cp.async.wait_group 1;" ::: "memory"); }
__device__ __forceinline__ void ldsm4(uint32_t* r, uint32_t a) {
    asm volatile("ldmatrix.sync.aligned.m8n8.x4.shared.b16 {%0,%1,%2,%3}, [%4];"
                 : "=r"(r[0]), "=r"(r[1]), "=r"(r[2]), "=r"(r[3]) : "r"(a));
}
__device__ __forceinline__ void mma_f16(float* d, const uint32_t* a, uint32_t b0, uint32_t b1) {
    asm volatile("mma.sync.aligned.m16n8k16.row.col.f32.f16.f16.f32 "
                 "{%0,%1,%2,%3}, {%4,%5,%6,%7}, {%8,%9}, {%0,%1,%2,%3};"
                 : "+f"(d[0]), "+f"(d[1]), "+f"(d[2]), "+f"(d[3])
                 : "r"(a[0]), "r"(a[1]), "r"(a[2]), "r"(a[3]), "r"(b0), "r"(b1));
}

// ---- prep 1: per-level transpose [n][c][p] -> [n][p][c] fp16, half2 stores ----
__global__ void transpose_kernel(const float* __restrict__ x, size_t xoff, int C, int HW) {
    __shared__ float tile[64][33];
    const int n = blockIdx.z, p0 = blockIdx.x * 32, c0 = blockIdx.y * 64;
    const int tx = threadIdx.x, ty = threadIdx.y;   // 32 x 8
    const float* xb = x + (size_t)n * C * HW + (size_t)c0 * HW;
    const bool pok_rd = (p0 + tx < HW);
#pragma unroll
    for (int k = 0; k < 8; k++) {
        const int cc = ty + 8 * k;
        tile[cc][tx] = pok_rd ? xb[(size_t)cc * HW + p0 + tx] : 0.f;
    }
    __syncthreads();
    __half* dst = g_xt + xoff + (size_t)n * HW * C + c0;
#pragma unroll
    for (int k = 0; k < 4; k++) {
        const int pl = ty + 8 * k;
        const int p = p0 + pl;
        if (p < HW) {
            const float lo = tile[2 * tx][pl];
            const float hi = tile[2 * tx + 1][pl];
            *reinterpret_cast<__half2*>(dst + (size_t)p * C + 2 * tx) =
                __floats2half2_rn(lo, hi);
        }
    }
}

// ---- prep 2: per-level weights -> [tap][o][c] fp16 + combined bias ----
__global__ void pack_w_kernel(const float* __restrict__ regw, const float* __restrict__ clsw,
                              const float* __restrict__ regb, const float* __restrict__ clsb,
                              size_t woff, int boff, int C, int A4, int Otot) {
    int idx = blockIdx.x * blockDim.x + threadIdx.x;
    if (idx >= Otot * C) return;
    if (idx < Otot) g_bias[boff + idx] = (idx < A4) ? regb[idx] : clsb[idx - A4];
    int c = idx % C, o = idx / C;
    const float* src = (o < A4) ? (regw + ((size_t)o * C + c) * 9)
                                : (clsw + ((size_t)(o - A4) * C + c) * 9);
#pragma unroll
    for (int tap = 0; tap < 9; tap++)
        g_wt[woff + ((size_t)tap * Otot + o) * C + c] = __float2half_rn(src[tap]);
}

// ---- fused GEMM over ALL levels: fp16 m16n8k16, CTA 128x128, k-chunk 64 ----
#define ROWB 144
#define PLA  18432
#define STG  36864

__global__ __launch_bounds__(256, 2)
void gemm_kernel(float* __restrict__ out) {
    extern __shared__ char dsm[];
    const uint32_t sb = smem_u32(dsm);
    const int bid = blockIdx.x;

    int lvl = 0;
#pragma unroll
    for (int i = 1; i < 6; i++) if (bid >= c_cum[i]) lvl = i;
    const int C = c_C[lvl], H = c_S[lvl], W = H, A = c_A[lvl];
    const int Otot = 95 * A, P = c_P[lvl], M = H * W;
    const size_t xoff = c_xoff[lvl], woff = c_woff[lvl];
    const int boff = c_boff[lvl];
    const int tl = bid - c_cum[lvl];
    const int ntO = c_ntO[lvl];
    const int o0 = (tl % ntO) * 128, m0 = (tl / ntO) * 128;

    const int HW = M, KC = C >> 6, nchunks = 9 * KC;
    const int t = threadIdx.x, warp = t >> 5, lane = t & 31;
    const int MT = BATCH * M, A4 = 4 * A;
    const int mwarp = warp >> 2, nwarp = warp & 3;
    const int kofs = warp & 3;

    // warp-uniform liveness: entire 32-col N-slice / 64-row M-slice padding?
    const bool wlive = (o0 + nwarp * 32 < Otot) && (m0 + mwarp * 64 < MT);

    const int r = t >> 1, chalf = t & 1;
    const int ma = m0 + r;
    const bool avalid = (ma < MT);
    const int mm = avalid ? ma : 0;
    const int na = mm / M, pa = mm - na * M;
    const int ah_ = pa / W, aw_ = pa - ah_ * W;
    const size_t a_nbase = (size_t)na * HW * C;
    const int ob = o0 + r;
    const bool bvalid = (ob < Otot);
    const size_t b_obase = (size_t)(bvalid ? ob : 0) * C;
    const size_t OC = (size_t)Otot * C;
    const uint32_t dst_r = (uint32_t)r * ROWB + (uint32_t)chalf * 64;

    float acc[4][4][4];
#pragma unroll
    for (int i = 0; i < 4; i++)
#pragma unroll
        for (int j = 0; j < 4; j++)
#pragma unroll
            for (int k = 0; k < 4; k++) acc[i][j][k] = 0.f;

    const uint32_t a_lmrow = (uint32_t)(mwarp * 64 + (lane & 15)) * ROWB + ((lane >> 4) * 16);
    const int nl = (lane & 7) + ((lane >> 4) << 3);
    const uint32_t b_lmrow = (uint32_t)(nwarp * 32 + nl) * ROWB + (((lane >> 3) & 1) * 16);

#define LOAD_CHUNK(ch) {                                                            \
    const int s_ = (ch) % 3;                                                        \
    const int tap = (ch) / KC, ck = (ch) - tap * KC;                                \
    const int dy = tap / 3 - 1, dx = tap % 3 - 1;                                   \
    const int hh = ah_ + dy, ww = aw_ + dx;                                         \
    const bool aok = avalid && hh >= 0 && hh < H && ww >= 0 && ww < W;              \
    const size_t asrc = xoff + a_nbase + (size_t)(aok ? (hh * W + ww) : 0) * C      \
                        + (ck << 6) + chalf * 32;                                   \
    const size_t bsrc = woff + (size_t)tap * OC + b_obase + (ck << 6) + chalf * 32; \
    const uint32_t az = aok ? 16u : 0u, bz = bvalid ? 16u : 0u;                     \
    const uint32_t d0 = sb + s_ * STG + dst_r;                                      \
    _Pragma("unroll")                                                               \
    for (int c = 0; c < 4; c++) {                                                   \
        cp16(d0 + c * 16,       g_xt + asrc + c * 8, az);                           \
        cp16(d0 + PLA + c * 16, g_wt + bsrc + c * 8, bz);                           \
    }                                                                               \
    cp_commit(); }

    LOAD_CHUNK(0)
    LOAD_CHUNK(1)

    for (int ch = 0; ch < nchunks; ch++) {
        cp_wait1();
        __syncthreads();
        if (ch + 2 < nchunks) { LOAD_CHUNK(ch + 2) }
        else cp_commit();

        if (wlive) {
            const uint32_t base = sb + (ch % 3) * STG;
#pragma unroll
            for (int ks4 = 0; ks4 < 4; ks4++) {
                const uint32_t ko = (uint32_t)((ks4 + kofs) & 3) * 32;
                uint32_t ah[4][4], bf[2][4];
#pragma unroll
                for (int mt = 0; mt < 4; mt++)
                    ldsm4(ah[mt], base + a_lmrow + mt * (16 * ROWB) + ko);
#pragma unroll
                for (int bp = 0; bp < 2; bp++)
                    ldsm4(bf[bp], base + PLA + b_lmrow + bp * (16 * ROWB) + ko);
#pragma unroll
                for (int mt = 0; mt < 4; mt++)
#pragma unroll
                    for (int nt = 0; nt < 4; nt++) {
                        const int bp = nt >> 1, su = (nt & 1) * 2;
                        mma_f16(acc[mt][nt], ah[mt], bf[bp][su], bf[bp][su + 1]);
                    }
            }
        }
    }

    // ---- epilogue ----
    float* bbox = out;
    float* cls  = out + CLS_OFF;
#pragma unroll
    for (int mt = 0; mt < 4; mt++) {
#pragma unroll
        for (int half = 0; half < 2; half++) {
            const int m = m0 + mwarp * 64 + mt * 16 + (lane >> 2) + half * 8;
            if (m >= MT) continue;
            const int n = m / M, p = m - n * M;
            const size_t obase = (size_t)n * NPOS + P + (size_t)p * A;
#pragma unroll
            for (int nt = 0; nt < 4; nt++) {
#pragma unroll
                for (int e = 0; e < 2; e++) {
                    const int o = o0 + nwarp * 32 + nt * 8 + (lane & 3) * 2 + e;
                    if (o >= Otot) continue;
                    float v = acc[mt][nt][half * 2 + e] + g_bias[boff + o];
                    if (o < A4)
                        bbox[(obase + (o >> 2)) * 4 + (o & 3)] = v;
                    else {
                        const int q = o - A4;
                        const int a = q / 91;
                        cls[(obase + a) * 91 + (q - a * 91)] = v;
                    }
                }
            }
        }
    }
}

// ------------------------------- launch ------------------------------------
extern "C" void kernel_launch(void* const* d_in, const int* in_sizes, int n_in,
                              void* d_out, int out_size) {
    static const int    Cs[6]   = {512, 1024, 512, 256, 256, 256};
    static const int    Ss[6]   = {38, 19, 10, 5, 3, 1};
    static const int    Aa[6]   = {4, 6, 6, 6, 4, 4};
    static const int    BOFF[6] = {0, 380, 950, 1520, 2090, 2470};
    static const size_t XOFF[6] = {0, 23658496, 35487744, 37126144, 37330944, 37404672};
    static const size_t WOFF[6] = {0, 1751040, 7004160, 9630720, 10944000, 11819520};
    const int SMEM = 3 * STG;   // 110592

    cudaFuncSetAttribute(gemm_kernel, cudaFuncAttributeMaxDynamicSharedMemorySize, SMEM);
    float* out = (float*)d_out;

    for (int i = 0; i < 6; i++) {
        const int C = Cs[i], S = Ss[i], A = Aa[i];
        const int HW = S * S, Otot = 95 * A, A4 = 4 * A;
        const float* feat = (const float*)d_in[5 * i + 0];
        const float* clsw = (const float*)d_in[5 * i + 1];
        const float* clsb = (const float*)d_in[5 * i + 2];
        const float* regw = (const float*)d_in[5 * i + 3];
        const float* regb = (const float*)d_in[5 * i + 4];
        dim3 tg((HW + 31) / 32, C / 64, BATCH);
        transpose_kernel<<<tg, dim3(32, 8)>>>(feat, XOFF[i], C, HW);
        pack_w_kernel<<<(Otot * C + 255) / 256, 256>>>(regw, clsw, regb, clsb,
                                                       WOFF[i], BOFF[i], C, A4, Otot);
    }

    gemm_kernel<<<1710, 256, SMEM>>>(out);
}

// round 16
// speedup vs baseline: 1.0614x; 1.0614x over previous
#include <cuda_runtime.h>
#include <cuda_fp16.h>
#include <stdint.h>

#define BATCH 32
#define NPOS  8732
#define CLS_OFF ((size_t)BATCH * NPOS * 4)

// static scratch
__device__ __half g_xt[37412864];
__device__ __half g_wt[12695040];
__device__ float  g_bias[2850];

// per-level tables (L0..L5)
// GEMM tile schedule: LPT order — L1 (144-chunk tiles) first, then L0, L2..L5
__constant__ int    c_cum[7]   = {0, 455, 1538, 1663, 1698, 1707, 1710};
__constant__ int    c_glvl[6]  = {1, 0, 2, 3, 4, 5};
__constant__ int    c_ntO[6]   = {3, 5, 5, 5, 3, 3};
__constant__ int    c_C[6]     = {512, 1024, 512, 256, 256, 256};
__constant__ int    c_S[6]     = {38, 19, 10, 5, 3, 1};
__constant__ int    c_A[6]     = {4, 6, 6, 6, 4, 4};
__constant__ int    c_P[6]     = {0, 5776, 7942, 8542, 8692, 8728};
__constant__ int    c_boff[6]  = {0, 380, 950, 1520, 2090, 2470};
__constant__ size_t c_xoff[6]  = {0, 23658496, 35487744, 37126144, 37330944, 37404672};
__constant__ size_t c_woff[6]  = {0, 1751040, 7004160, 9630720, 10944000, 11819520};

__device__ __forceinline__ uint32_t smem_u32(const void* p) {
    uint32_t r;
    asm("{ .reg .u64 t; cvta.to.shared.u64 t, %1; cvt.u32.u64 %0, t; }" : "=r"(r) : "l"(p));
    return r;
}
__device__ __forceinline__ void cp16(uint32_t dst, const void* src, uint32_t sz) {
    asm volatile("cp.async.cg.shared.global [%0], [%1], 16, %2;"
                 :: "r"(dst), "l"(src), "r"(sz) : "memory");
}
__device__ __forceinline__ void cp_commit() { asm volatile("cp.async.commit_group;" ::: "memory"); }
__device__ __forceinline__ void cp_wait1()  { asm volatile("cp.async.wait_group 1;" ::: "memory"); }
__device__ __forceinline__ void ldsm4(uint32_t* r, uint32_t a) {
    asm volatile("ldmatrix.sync.aligned.m8n8.x4.shared.b16 {%0,%1,%2,%3}, [%4];"
                 : "=r"(r[0]), "=r"(r[1]), "=r"(r[2]), "=r"(r[3]) : "r"(a));
}
__device__ __forceinline__ void mma_f16(float* d, const uint32_t* a, uint32_t b0, uint32_t b1) {
    asm volatile("mma.sync.aligned.m16n8k16.row.col.f32.f16.f16.f32 "
                 "{%0,%1,%2,%3}, {%4,%5,%6,%7}, {%8,%9}, {%0,%1,%2,%3};"
                 : "+f"(d[0]), "+f"(d[1]), "+f"(d[2]), "+f"(d[3])
                 : "r"(a[0]), "r"(a[1]), "r"(a[2]), "r"(a[3]), "r"(b0), "r"(b1));
}

// ---- prep 1: per-level transpose [n][c][p] -> [n][p][c] fp16, half2 stores ----
__global__ void transpose_kernel(const float* __restrict__ x, size_t xoff, int C, int HW) {
    __shared__ float tile[64][33];
    const int n = blockIdx.z, p0 = blockIdx.x * 32, c0 = blockIdx.y * 64;
    const int tx = threadIdx.x, ty = threadIdx.y;   // 32 x 8
    const float* xb = x + (size_t)n * C * HW + (size_t)c0 * HW;
    const bool pok_rd = (p0 + tx < HW);
#pragma unroll
    for (int k = 0; k < 8; k++) {
        const int cc = ty + 8 * k;
        tile[cc][tx] = pok_rd ? xb[(size_t)cc * HW + p0 + tx] : 0.f;
    }
    __syncthreads();
    __half* dst = g_xt + xoff + (size_t)n * HW * C + c0;
#pragma unroll
    for (int k = 0; k < 4; k++) {
        const int pl = ty + 8 * k;
        const int p = p0 + pl;
        if (p < HW) {
            const float lo = tile[2 * tx][pl];
            const float hi = tile[2 * tx + 1][pl];
            *reinterpret_cast<__half2*>(dst + (size_t)p * C + 2 * tx) =
                __floats2half2_rn(lo, hi);
        }
    }
}

// ---- prep 2: per-level weights -> [tap][o][c] fp16 + combined bias ----
__global__ void pack_w_kernel(const float* __restrict__ regw, const float* __restrict__ clsw,
                              const float* __restrict__ regb, const float* __restrict__ clsb,
                              size_t woff, int boff, int C, int A4, int Otot) {
    int idx = blockIdx.x * blockDim.x + threadIdx.x;
    if (idx >= Otot * C) return;
    if (idx < Otot) g_bias[boff + idx] = (idx < A4) ? regb[idx] : clsb[idx - A4];
    int c = idx % C, o = idx / C;
    const float* src = (o < A4) ? (regw + ((size_t)o * C + c) * 9)
                                : (clsw + ((size_t)(o - A4) * C + c) * 9);
#pragma unroll
    for (int tap = 0; tap < 9; tap++)
        g_wt[woff + ((size_t)tap * Otot + o) * C + c] = __float2half_rn(src[tap]);
}

// ---- fused GEMM over ALL levels: fp16 m16n8k16, CTA 128x128, k-chunk 64 ----
#define ROWB 144
#define PLA  18432
#define STG  36864

__global__ __launch_bounds__(256, 2)
void gemm_kernel(float* __restrict__ out) {
    extern __shared__ char dsm[];
    const uint32_t sb = smem_u32(dsm);
    const int bid = blockIdx.x;

    int seg = 0;
#pragma unroll
    for (int i = 1; i < 6; i++) if (bid >= c_cum[i]) seg = i;
    const int lvl = c_glvl[seg];
    const int C = c_C[lvl], H = c_S[lvl], W = H, A = c_A[lvl];
    const int Otot = 95 * A, P = c_P[lvl], M = H * W;
    const size_t xoff = c_xoff[lvl], woff = c_woff[lvl];
    const int boff = c_boff[lvl];
    const int tl = bid - c_cum[seg];
    const int ntO = c_ntO[lvl];
    const int o0 = (tl % ntO) * 128, m0 = (tl / ntO) * 128;

    const int HW = M, KC = C >> 6, nchunks = 9 * KC;
    const int t = threadIdx.x, warp = t >> 5, lane = t & 31;
    const int MT = BATCH * M, A4 = 4 * A;
    const int mwarp = warp >> 2, nwarp = warp & 3;
    const int kofs = warp & 3;

    const int r = t >> 1, chalf = t & 1;
    const int ma = m0 + r;
    const bool avalid = (ma < MT);
    const int mm = avalid ? ma : 0;
    const int na = mm / M, pa = mm - na * M;
    const int ah_ = pa / W, aw_ = pa - ah_ * W;
    const size_t a_nbase = (size_t)na * HW * C;
    const int ob = o0 + r;
    const bool bvalid = (ob < Otot);
    const size_t b_obase = (size_t)(bvalid ? ob : 0) * C;
    const size_t OC = (size_t)Otot * C;
    const uint32_t dst_r = (uint32_t)r * ROWB + (uint32_t)chalf * 64;

    float acc[4][4][4];
#pragma unroll
    for (int i = 0; i < 4; i++)
#pragma unroll
        for (int j = 0; j < 4; j++)
#pragma unroll
            for (int k = 0; k < 4; k++) acc[i][j][k] = 0.f;

    const uint32_t a_lmrow = (uint32_t)(mwarp * 64 + (lane & 15)) * ROWB + ((lane >> 4) * 16);
    const int nl = (lane & 7) + ((lane >> 4) << 3);
    const uint32_t b_lmrow = (uint32_t)(nwarp * 32 + nl) * ROWB + (((lane >> 3) & 1) * 16);

#define LOAD_CHUNK(ch) {                                                            \
    const int s_ = (ch) % 3;                                                        \
    const int tap = (ch) / KC, ck = (ch) - tap * KC;                                \
    const int dy = tap / 3 - 1, dx = tap % 3 - 1;                                   \
    const int hh = ah_ + dy, ww = aw_ + dx;                                         \
    const bool aok = avalid && hh >= 0 && hh < H && ww >= 0 && ww < W;              \
    const size_t asrc = xoff + a_nbase + (size_t)(aok ? (hh * W + ww) : 0) * C      \
                        + (ck << 6) + chalf * 32;                                   \
    const size_t bsrc = woff + (size_t)tap * OC + b_obase + (ck << 6) + chalf * 32; \
    const uint32_t az = aok ? 16u : 0u, bz = bvalid ? 16u : 0u;                     \
    const uint32_t d0 = sb + s_ * STG + dst_r;                                      \
    _Pragma("unroll")                                                               \
    for (int c = 0; c < 4; c++) {                                                   \
        cp16(d0 + c * 16,       g_xt + asrc + c * 8, az);                           \
        cp16(d0 + PLA + c * 16, g_wt + bsrc + c * 8, bz);                           \
    }                                                                               \
    cp_commit(); }

    LOAD_CHUNK(0)
    LOAD_CHUNK(1)

    for (int ch = 0; ch < nchunks; ch++) {
        cp_wait1();
        __syncthreads();
        if (ch + 2 < nchunks) { LOAD_CHUNK(ch + 2) }
        else cp_commit();

        const uint32_t base = sb + (ch % 3) * STG;
#pragma unroll
        for (int ks4 = 0; ks4 < 4; ks4++) {
            const uint32_t ko = (uint32_t)((ks4 + kofs) & 3) * 32;
            uint32_t ah[4][4], bf[2][4];
#pragma unroll
            for (int mt = 0; mt < 4; mt++)
                ldsm4(ah[mt], base + a_lmrow + mt * (16 * ROWB) + ko);
#pragma unroll
            for (int bp = 0; bp < 2; bp++)
                ldsm4(bf[bp], base + PLA + b_lmrow + bp * (16 * ROWB) + ko);
#pragma unroll
            for (int mt = 0; mt < 4; mt++)
#pragma unroll
                for (int nt = 0; nt < 4; nt++) {
                    const int bp = nt >> 1, su = (nt & 1) * 2;
                    mma_f16(acc[mt][nt], ah[mt], bf[bp][su], bf[bp][su + 1]);
                }
        }
    }

    // ---- epilogue ----
    float* bbox = out;
    float* cls  = out + CLS_OFF;
#pragma unroll
    for (int mt = 0; mt < 4; mt++) {
#pragma unroll
        for (int half = 0; half < 2; half++) {
            const int m = m0 + mwarp * 64 + mt * 16 + (lane >> 2) + half * 8;
            if (m >= MT) continue;
            const int n = m / M, p = m - n * M;
            const size_t obase = (size_t)n * NPOS + P + (size_t)p * A;
#pragma unroll
            for (int nt = 0; nt < 4; nt++) {
#pragma unroll
                for (int e = 0; e < 2; e++) {
                    const int o = o0 + nwarp * 32 + nt * 8 + (lane & 3) * 2 + e;
                    if (o >= Otot) continue;
                    float v = acc[mt][nt][half * 2 + e] + g_bias[boff + o];
                    if (o < A4)
                        bbox[(obase + (o >> 2)) * 4 + (o & 3)] = v;
                    else {
                        const int q = o - A4;
                        const int a = q / 91;
                        cls[(obase + a) * 91 + (q - a * 91)] = v;
                    }
                }
            }
        }
    }
}

// ------------------------------- launch ------------------------------------
extern "C" void kernel_launch(void* const* d_in, const int* in_sizes, int n_in,
                              void* d_out, int out_size) {
    static const int    Cs[6]   = {512, 1024, 512, 256, 256, 256};
    static const int    Ss[6]   = {38, 19, 10, 5, 3, 1};
    static const int    Aa[6]   = {4, 6, 6, 6, 4, 4};
    static const int    BOFF[6] = {0, 380, 950, 1520, 2090, 2470};
    static const size_t XOFF[6] = {0, 23658496, 35487744, 37126144, 37330944, 37404672};
    static const size_t WOFF[6] = {0, 1751040, 7004160, 9630720, 10944000, 11819520};
    const int SMEM = 3 * STG;   // 110592

    cudaFuncSetAttribute(gemm_kernel, cudaFuncAttributeMaxDynamicSharedMemorySize, SMEM);
    float* out = (float*)d_out;

    for (int i = 0; i < 6; i++) {
        const int C = Cs[i], S = Ss[i], A = Aa[i];
        const int HW = S * S, Otot = 95 * A, A4 = 4 * A;
        const float* feat = (const float*)d_in[5 * i + 0];
        const float* clsw = (const float*)d_in[5 * i + 1];
        const float* clsb = (const float*)d_in[5 * i + 2];
        const float* regw = (const float*)d_in[5 * i + 3];
        const float* regb = (const float*)d_in[5 * i + 4];
        dim3 tg((HW + 31) / 32, C / 64, BATCH);
        transpose_kernel<<<tg, dim3(32, 8)>>>(feat, XOFF[i], C, HW);
        pack_w_kernel<<<(Otot * C + 255) / 256, 256>>>(regw, clsw, regb, clsb,
                                                       WOFF[i], BOFF[i], C, A4, Otot);
    }

    gemm_kernel<<<1710, 256, SMEM>>>(out);
}